// round 13
// baseline (speedup 1.0000x reference)
#include <cuda_runtime.h>

#define NPTS    2048
#define THREADS 128
#define GRPS    4                  // warps per CTA
#define NI      4                  // i's per thread (optimal ILP)
#define IPB     (GRPS*NI)          // 16 i's per CTA
#define JHALF   (NPTS/2)           // 1024 j's per CTA (j-split)
#define EPS     1e-5f
#define BIAS    1e-5f              // sq bias (diagonal-safe, absorbs dot-form cancellation)

__global__ void zero_kernel(float* __restrict__ o, int n) {
    const int i = blockIdx.x * blockDim.x + threadIdx.x;
    if (i < n) o[i] = 0.f;
}

__global__ __launch_bounds__(THREADS, 6) void spring_kernel(
    const float* __restrict__ X, const float* __restrict__ Kp,
    const float* __restrict__ Bp, float* __restrict__ out)
{
    __shared__ float4 xs[JHALF];
    __shared__ float4 red[GRPS];
    const int b   = blockIdx.y;
    const int jh  = blockIdx.z;          // which j-half this CTA sums
    const int tid = threadIdx.x;
    const float* Xb = X + (size_t)b * NPTS * 3;
    const float* Xh = Xb + (size_t)jh * JHALF * 3;

    // Stage this CTA's j-half into SMEM as (x, y, z, |p|^2) + partials of S_half.
    float sx = 0.f, sy = 0.f, sz = 0.f;
    for (int p = tid; p < JHALF; p += THREADS) {
        const float x = Xh[3*p], y = Xh[3*p+1], z = Xh[3*p+2];
        xs[p] = make_float4(x, y, z, fmaf(x, x, fmaf(y, y, z*z)));
        sx += x; sy += y; sz += z;
    }
    #pragma unroll
    for (int m = 16; m >= 1; m >>= 1) {
        sx += __shfl_xor_sync(0xffffffffu, sx, m);
        sy += __shfl_xor_sync(0xffffffffu, sy, m);
        sz += __shfl_xor_sync(0xffffffffu, sz, m);
    }
    if ((tid & 31) == 0) red[tid >> 5] = make_float4(sx, sy, sz, 0.f);
    __syncthreads();
    float4 S = make_float4(0.f, 0.f, 0.f, 0.f);
    #pragma unroll
    for (int wdx = 0; wdx < GRPS; wdx++) {
        S.x += red[wdx].x; S.y += red[wdx].y; S.z += red[wdx].z;
    }

    const float K = *Kp;
    const float c = K * (*Bp + EPS);     // f = K - c*w,  w ~= rsqrt(sq)

    const int grp   = tid >> 5;          // warp id, 0..3
    const int slice = tid & 31;          // lane
    const int ib = blockIdx.x * IPB + grp;

    // 4 i's per thread, GRPS apart; pi read from gmem (xs holds only the j-half).
    float m2x[NI], m2y[NI], m2z[NI], base[NI];
    float sr[NI], hpx[NI], hpy[NI], hpz[NI];
    #pragma unroll
    for (int q = 0; q < NI; q++) {
        const int i = ib + q * GRPS;
        const float x = Xb[3*i], y = Xb[3*i+1], z = Xb[3*i+2];
        m2x[q] = -2.f * x; m2y[q] = -2.f * y; m2z[q] = -2.f * z;
        base[q] = fmaf(x, x, fmaf(y, y, z*z)) + BIAS;
        sr[q] = 0.f; hpx[q] = 0.f; hpy[q] = 0.f; hpz[q] = 0.f;
    }

    // 32 lanes read 32 consecutive float4s: conflict-free LDS.128.
    //   sq = (|pi|^2 + bias - 2 pi.pj) + |pj|^2
    //   h  = (sum r)*pi - sum(r*pj)
    #pragma unroll 8
    for (int j = slice; j < JHALF; j += 32) {
        const float4 pj = xs[j];
        #pragma unroll
        for (int q = 0; q < NI; q++) {
            float t = fmaf(m2x[q], pj.x, base[q]);
            const float u = fmaf(m2y[q], pj.y, pj.w);
            t = fmaf(m2z[q], pj.z, t);
            const float r = rsqrtf(t + u);
            sr[q] += r;
            hpx[q] = fmaf(r, pj.x, hpx[q]);
            hpy[q] = fmaf(r, pj.y, hpy[q]);
            hpz[q] = fmaf(r, pj.z, hpz[q]);
        }
    }

    // Warp reduction over the 32 j-slices.
    #pragma unroll
    for (int m = 1; m < 32; m <<= 1) {
        #pragma unroll
        for (int q = 0; q < NI; q++) {
            sr[q]  += __shfl_xor_sync(0xffffffffu, sr[q],  m);
            hpx[q] += __shfl_xor_sync(0xffffffffu, hpx[q], m);
            hpy[q] += __shfl_xor_sync(0xffffffffu, hpy[q], m);
            hpz[q] += __shfl_xor_sync(0xffffffffu, hpz[q], m);
        }
    }

    if (slice == 0) {
        #pragma unroll
        for (int q = 0; q < NI; q++) {
            const int i = ib + q * GRPS;
            const float px = -0.5f * m2x[q];   // exact recovery of pi
            const float py = -0.5f * m2y[q];
            const float pz = -0.5f * m2z[q];
            // per-half contribution: K*(JHALF*pi - S_half) - c*(sr*pi - hp)
            // half 0 additionally carries the +pi identity term.
            const float idf = (jh == 0) ? 1.f : 0.f;
            float vx = fmaf(K, fmaf((float)JHALF, px, -S.x), fmaf(-c, fmaf(sr[q], px, -hpx[q]), idf * px));
            float vy = fmaf(K, fmaf((float)JHALF, py, -S.y), fmaf(-c, fmaf(sr[q], py, -hpy[q]), idf * py));
            float vz = fmaf(K, fmaf((float)JHALF, pz, -S.z), fmaf(-c, fmaf(sr[q], pz, -hpz[q]), idf * pz));
            float* o = out + ((size_t)b * NPTS + i) * 3;
            atomicAdd(&o[0], vx);
            atomicAdd(&o[1], vy);
            atomicAdd(&o[2], vz);
        }
    }
}

extern "C" void kernel_launch(void* const* d_in, const int* in_sizes, int n_in,
                              void* d_out, int out_size) {
    const float* X = (const float*)d_in[0];
    const float* K = (const float*)d_in[1];
    const float* B = (const float*)d_in[2];
    float* out = (float*)d_out;

    const int batch = in_sizes[0] / (NPTS * 3);

    zero_kernel<<<(out_size + 255) / 256, 256>>>(out, out_size);

    dim3 grid(NPTS / IPB, batch, 2);   // 128 x 4 x 2 = 1024 CTAs
    spring_kernel<<<grid, THREADS>>>(X, K, B, out);
}

// round 14
// speedup vs baseline: 1.3636x; 1.3636x over previous
#include <cuda_runtime.h>

#define NPTS    2048
#define THREADS 256
#define SLICES  64                 // j-slices per i (2 warps cooperate)
#define GRPS    (THREADS/SLICES)   // 4 i-groups per CTA
#define NI      4                  // i's per thread (optimal ILP)
#define IPB     (GRPS*NI)          // 16 i's per CTA -> 128 x 4 = 512 CTAs
#define EPS     1e-5f
#define BIAS    1e-5f              // sq bias (diagonal-safe, absorbs dot-form cancellation)

__global__ __launch_bounds__(THREADS, 4) void spring_kernel(
    const float* __restrict__ X, const float* __restrict__ Kp,
    const float* __restrict__ Bp, float* __restrict__ out)
{
    __shared__ float4 xs[NPTS];
    __shared__ float4 red[THREADS / 32];
    __shared__ float  cred[THREADS / 32][4 * NI];
    const int b   = blockIdx.y;
    const int tid = threadIdx.x;
    const float* Xb = X + (size_t)b * NPTS * 3;

    // Stage batch into SMEM as (x, y, z, |p|^2) + partial sums for S = sum_j x_j.
    float sx = 0.f, sy = 0.f, sz = 0.f;
    for (int p = tid; p < NPTS; p += THREADS) {
        const float x = Xb[3*p], y = Xb[3*p+1], z = Xb[3*p+2];
        xs[p] = make_float4(x, y, z, fmaf(x, x, fmaf(y, y, z*z)));
        sx += x; sy += y; sz += z;
    }
    #pragma unroll
    for (int m = 16; m >= 1; m >>= 1) {
        sx += __shfl_xor_sync(0xffffffffu, sx, m);
        sy += __shfl_xor_sync(0xffffffffu, sy, m);
        sz += __shfl_xor_sync(0xffffffffu, sz, m);
    }
    if ((tid & 31) == 0) red[tid >> 5] = make_float4(sx, sy, sz, 0.f);
    __syncthreads();
    float4 S = make_float4(0.f, 0.f, 0.f, 0.f);
    #pragma unroll
    for (int wdx = 0; wdx < THREADS / 32; wdx++) {
        S.x += red[wdx].x; S.y += red[wdx].y; S.z += red[wdx].z;
    }

    const float K = *Kp;
    const float c = K * (*Bp + EPS);   // f = K - c*w,  w ~= rsqrt(sq)

    const int grp   = tid / SLICES;    // i-group, 0..3 (2 warps per group)
    const int slice = tid % SLICES;    // 0..63
    const int wid   = tid >> 5;        // warp id, 0..7
    const int lane  = tid & 31;
    const int ib = blockIdx.x * IPB + grp;

    // 4 i's per thread, GRPS apart.
    float m2x[NI], m2y[NI], m2z[NI], base[NI];
    float sr[NI], hpx[NI], hpy[NI], hpz[NI];
    #pragma unroll
    for (int q = 0; q < NI; q++) {
        const float4 v = xs[ib + q * GRPS];
        m2x[q] = -2.f * v.x; m2y[q] = -2.f * v.y; m2z[q] = -2.f * v.z;
        base[q] = v.w + BIAS;
        sr[q] = 0.f; hpx[q] = 0.f; hpy[q] = 0.f; hpz[q] = 0.f;
    }

    // 64 lanes (2 warps) cover 64 consecutive float4s: conflict-free LDS.128.
    //   sq = (|pi|^2 + bias - 2 pi.pj) + |pj|^2
    //   h  = (sum r)*pi - sum(r*pj)
    #pragma unroll 4
    for (int j = slice; j < NPTS; j += SLICES) {
        const float4 pj = xs[j];
        #pragma unroll
        for (int q = 0; q < NI; q++) {
            float t = fmaf(m2x[q], pj.x, base[q]);
            const float u = fmaf(m2y[q], pj.y, pj.w);
            t = fmaf(m2z[q], pj.z, t);
            const float r = rsqrtf(t + u);
            sr[q] += r;
            hpx[q] = fmaf(r, pj.x, hpx[q]);
            hpy[q] = fmaf(r, pj.y, hpy[q]);
            hpz[q] = fmaf(r, pj.z, hpz[q]);
        }
    }

    // Intra-warp reduction over 32 of the 64 j-slices.
    #pragma unroll
    for (int m = 1; m < 32; m <<= 1) {
        #pragma unroll
        for (int q = 0; q < NI; q++) {
            sr[q]  += __shfl_xor_sync(0xffffffffu, sr[q],  m);
            hpx[q] += __shfl_xor_sync(0xffffffffu, hpx[q], m);
            hpy[q] += __shfl_xor_sync(0xffffffffu, hpy[q], m);
            hpz[q] += __shfl_xor_sync(0xffffffffu, hpz[q], m);
        }
    }
    if (lane == 0) {
        #pragma unroll
        for (int q = 0; q < NI; q++) {
            cred[wid][q*4+0] = sr[q];
            cred[wid][q*4+1] = hpx[q];
            cred[wid][q*4+2] = hpy[q];
            cred[wid][q*4+3] = hpz[q];
        }
    }
    __syncthreads();

    // Warp-pair combine: even warp's lane 0 finishes its group's 4 i's.
    if (lane == 0 && (wid & 1) == 0) {
        #pragma unroll
        for (int q = 0; q < NI; q++) {
            const float srq = cred[wid][q*4+0] + cred[wid+1][q*4+0];
            const float hxq = cred[wid][q*4+1] + cred[wid+1][q*4+1];
            const float hyq = cred[wid][q*4+2] + cred[wid+1][q*4+2];
            const float hzq = cred[wid][q*4+3] + cred[wid+1][q*4+3];
            const int i = ib + q * GRPS;
            const float4 v = xs[i];
            const float hxv = fmaf(srq, v.x, -hxq);
            const float hyv = fmaf(srq, v.y, -hyq);
            const float hzv = fmaf(srq, v.z, -hzq);
            float* o = out + ((size_t)b * NPTS + i) * 3;
            o[0] = fmaf(K, fmaf((float)NPTS, v.x, -S.x), fmaf(-c, hxv, v.x));
            o[1] = fmaf(K, fmaf((float)NPTS, v.y, -S.y), fmaf(-c, hyv, v.y));
            o[2] = fmaf(K, fmaf((float)NPTS, v.z, -S.z), fmaf(-c, hzv, v.z));
        }
    }
}

extern "C" void kernel_launch(void* const* d_in, const int* in_sizes, int n_in,
                              void* d_out, int out_size) {
    const float* X = (const float*)d_in[0];
    const float* K = (const float*)d_in[1];
    const float* B = (const float*)d_in[2];
    float* out = (float*)d_out;

    const int batch = in_sizes[0] / (NPTS * 3);
    dim3 grid(NPTS / IPB, batch);   // 128 x 4 = 512 CTAs
    spring_kernel<<<grid, THREADS>>>(X, K, B, out);
}